// round 4
// baseline (speedup 1.0000x reference)
#include <cuda_runtime.h>
#include <cstddef>

// ---------------------------------------------------------------------------
// CarbonGNN: GCNConv -> ReLU -> GATv2Conv(heads=4, concat=False) -> ReLU -> Linear
// N=50000, E=800000, IN=128, HID=64, H=4, neg_slope=0.2
// ---------------------------------------------------------------------------

#define MAXN 50000
#define MAXE 800000

// Scratch (device globals: allocation-free)
__device__ float    d_xw[MAXN * 64];            // x @ W_gcn
__device__ float    d_g1[MAXN * 64];            // GCN aggregation (pre-bias/relu)
__device__ float    d_dinv[MAXN];
__device__ int      d_deg[MAXN];
__device__ float    d_xl[MAXN * 256];           // lin_l(h)  [N, H*HID]
__device__ float    d_xr[MAXN * 256];           // lin_r(h)
__device__ float    d_p[(MAXE + MAXN) * 4];     // logits, then p=exp(logit-m)
__device__ unsigned d_menc[MAXN * 4];           // encoded segment max
__device__ float    d_denom[MAXN * 4];
__device__ float    d_acc[MAXN * 256];          // GAT message accumulator [N,H,HID]

// Monotonic float <-> uint encoding for atomicMax on floats
__device__ __forceinline__ unsigned fenc(float f) {
    unsigned u = __float_as_uint(f);
    return (u >> 31) ? ~u : (u | 0x80000000u);
}
__device__ __forceinline__ float fdec(unsigned e) {
    return (e >> 31) ? __uint_as_float(e & 0x7fffffffu) : __uint_as_float(~e);
}

// ---------------------------------------------------------------------------
// Zero init for per-call accumulators (float4-vectorized on the big array)
__global__ void k_zero(int n) {
    int i = blockIdx.x * blockDim.x + threadIdx.x;
    if (i < n * 64)   // n*256 floats / 4
        ((float4*)d_acc)[i] = make_float4(0.f, 0.f, 0.f, 0.f);
    if (i < n * 4) { d_menc[i] = 0u; d_denom[i] = 0.f; }
    if (i < n) d_deg[i] = 0;
}

// ---------------------------------------------------------------------------
// Tiled fp32 GEMM: C[M,NC] = act(A[M,BK]) @ W[BK,NC] (+bout)
// act = relu(a + bin[k]) if RELU_IN else identity
// Block = 128 threads, tile 32 rows x 64 cols, k-chunks of 32.
template <int BK, bool RELU_IN>
__device__ __forceinline__ void gemm_body(
    const float* __restrict__ A, const float* __restrict__ W,
    const float* __restrict__ bin, const float* __restrict__ bout,
    float* __restrict__ C, int M, int NC)
{
    __shared__ float As[32 * 32];
    __shared__ float Ws[32 * 64];
    const int t = threadIdx.x;
    const int row0 = blockIdx.x * 32;
    const int c0 = blockIdx.y * 64;
    const int tc = t & 15;          // 0..15 -> 4 cols each
    const int tr = t >> 4;          // 0..7  -> 4 rows each
    float acc[4][4] = {};

    for (int kc = 0; kc < BK; kc += 32) {
        // load A tile: 32 rows x 32 k
        {
            int r = t >> 2, q4 = t & 3;
            int grow = row0 + r;
            #pragma unroll
            for (int half = 0; half < 2; half++) {
                int q = q4 + half * 4;        // 0..7 float4 slots per row
                float4 v = make_float4(0.f, 0.f, 0.f, 0.f);
                if (grow < M)
                    v = *(const float4*)(A + (size_t)grow * BK + kc + q * 4);
                if (RELU_IN) {
                    const float* bb = bin + kc + q * 4;
                    v.x = fmaxf(v.x + bb[0], 0.f);
                    v.y = fmaxf(v.y + bb[1], 0.f);
                    v.z = fmaxf(v.z + bb[2], 0.f);
                    v.w = fmaxf(v.w + bb[3], 0.f);
                }
                *(float4*)(As + r * 32 + q * 4) = v;
            }
        }
        // load W tile: 32 k x 64 cols
        {
            int k = t >> 4, q2 = t & 15;
            #pragma unroll
            for (int i = 0; i < 4; i++) {
                int kk = k + i * 8;
                *(float4*)(Ws + kk * 64 + q2 * 4) =
                    *(const float4*)(W + (size_t)(kc + kk) * NC + c0 + q2 * 4);
            }
        }
        __syncthreads();
        #pragma unroll
        for (int kk = 0; kk < 32; kk += 4) {
            float4 a[4], w[4];
            #pragma unroll
            for (int r = 0; r < 4; r++)
                a[r] = *(const float4*)(As + (tr * 4 + r) * 32 + kk);
            #pragma unroll
            for (int j = 0; j < 4; j++)
                w[j] = *(const float4*)(Ws + (kk + j) * 64 + tc * 4);
            #pragma unroll
            for (int r = 0; r < 4; r++) {
                acc[r][0] += a[r].x * w[0].x + a[r].y * w[1].x + a[r].z * w[2].x + a[r].w * w[3].x;
                acc[r][1] += a[r].x * w[0].y + a[r].y * w[1].y + a[r].z * w[2].y + a[r].w * w[3].y;
                acc[r][2] += a[r].x * w[0].z + a[r].y * w[1].z + a[r].z * w[2].z + a[r].w * w[3].z;
                acc[r][3] += a[r].x * w[0].w + a[r].y * w[1].w + a[r].z * w[2].w + a[r].w * w[3].w;
            }
        }
        __syncthreads();
    }

    #pragma unroll
    for (int r = 0; r < 4; r++) {
        int grow = row0 + tr * 4 + r;
        if (grow < M) {
            float4 o = make_float4(acc[r][0], acc[r][1], acc[r][2], acc[r][3]);
            if (bout) {
                const float* bb = bout + c0 + tc * 4;
                o.x += bb[0]; o.y += bb[1]; o.z += bb[2]; o.w += bb[3];
            }
            *(float4*)(C + (size_t)grow * NC + c0 + tc * 4) = o;
        }
    }
}

__global__ void k_gemm_gcn(const float* __restrict__ x,
                           const float* __restrict__ Wg, int M) {
    gemm_body<128, false>(x, Wg, nullptr, nullptr, d_xw, M, 64);
}

__global__ void k_gemm_gat(const float* __restrict__ Wlr,
                           const float* __restrict__ bgcn,
                           const float* __restrict__ blr, int which, int M) {
    gemm_body<64, true>(d_g1, Wlr, bgcn, blr, which ? d_xr : d_xl, M, 256);
}

// ---------------------------------------------------------------------------
// GCN: degree, norm, aggregation
__global__ void k_deg(const int* __restrict__ dst, int E) {
    int e = blockIdx.x * blockDim.x + threadIdx.x;
    if (e < E) atomicAdd(&d_deg[__ldg(dst + e)], 1);
}

__global__ void k_dinv(int N) {
    int i = blockIdx.x * blockDim.x + threadIdx.x;
    if (i < N) d_dinv[i] = rsqrtf((float)d_deg[i] + 1.0f);  // +1 self loop
}

// self loop term: g1[i,:] = xw[i,:] * dinv[i]^2
__global__ void k_gcn_init(int N) {
    int idx = blockIdx.x * blockDim.x + threadIdx.x;
    if (idx < N * 64) {
        int i = idx >> 6;
        float di = d_dinv[i];
        d_g1[idx] = d_xw[idx] * di * di;
    }
}

// edge contributions: g1[d,:] += xw[s,:] * dinv[s]*dinv[d]  (16 thr/edge, float4)
__global__ void k_gcn_edge(const int* __restrict__ src,
                           const int* __restrict__ dst, int E) {
    int t = blockIdx.x * blockDim.x + threadIdx.x;
    int e = t >> 4;
    if (e >= E) return;
    int l = t & 15;
    int s = __ldg(src + e), d = __ldg(dst + e);
    float cf = d_dinv[s] * d_dinv[d];
    float4 v = *(const float4*)(d_xw + (size_t)s * 64 + l * 4);
    float* gp = d_g1 + (size_t)d * 64 + l * 4;
    atomicAdd(gp + 0, v.x * cf);
    atomicAdd(gp + 1, v.y * cf);
    atomicAdd(gp + 2, v.z * cf);
    atomicAdd(gp + 3, v.w * cf);
}

// ---------------------------------------------------------------------------
// GATv2 pass 1: per-edge logits + segment max (warp per edge, E+N edges incl. loops)
// Value layout v = h*64+c; lane owns float4 at v=4*lane (head lane>>4) and
// v=128+4*lane (head 2+(lane>>4)).
__global__ void k_logits(const int* __restrict__ src, const int* __restrict__ dst,
                         const float* __restrict__ att, int E, int N) {
    __shared__ float satt[256];
    if (threadIdx.x < 256) satt[threadIdx.x] = att[threadIdx.x];
    __syncthreads();
    int warp = (blockIdx.x * blockDim.x + threadIdx.x) >> 5;
    int lane = threadIdx.x & 31;
    int tot = E + N;
    if (warp >= tot) return;
    int s, d;
    if (warp < E) { s = __ldg(src + warp); d = __ldg(dst + warp); }
    else { s = d = warp - E; }

    const float4* xls = (const float4*)(d_xl + (size_t)s * 256);
    const float4* xrd = (const float4*)(d_xr + (size_t)d * 256);
    const float4* at4 = (const float4*)satt;
    float4 a1 = xls[lane],       b1 = xrd[lane],       t1 = at4[lane];
    float4 a2 = xls[lane + 32],  b2 = xrd[lane + 32],  t2 = at4[lane + 32];

    auto lr = [](float v) { return v > 0.f ? v : 0.2f * v; };
    float p1 = lr(a1.x + b1.x) * t1.x + lr(a1.y + b1.y) * t1.y
             + lr(a1.z + b1.z) * t1.z + lr(a1.w + b1.w) * t1.w;
    float p2 = lr(a2.x + b2.x) * t2.x + lr(a2.y + b2.y) * t2.y
             + lr(a2.z + b2.z) * t2.z + lr(a2.w + b2.w) * t2.w;

    // reduce within 16-lane half-warps (heads: lanes 0-15 -> {0,2}, 16-31 -> {1,3})
    #pragma unroll
    for (int m = 8; m; m >>= 1) {
        p1 += __shfl_xor_sync(0xffffffffu, p1, m);
        p2 += __shfl_xor_sync(0xffffffffu, p2, m);
    }
    if ((lane & 15) == 0) {
        int h = lane >> 4;
        size_t base = (size_t)warp * 4;
        d_p[base + h] = p1;
        d_p[base + 2 + h] = p2;
        atomicMax(&d_menc[(size_t)d * 4 + h], fenc(p1));
        atomicMax(&d_menc[(size_t)d * 4 + 2 + h], fenc(p2));
    }
}

// pass 2: p = exp(logit - m[d]); denom[d] += p
__global__ void k_softmax(const int* __restrict__ dst, int E, int N) {
    int idx = blockIdx.x * blockDim.x + threadIdx.x;
    int tot = (E + N) * 4;
    if (idx >= tot) return;
    int e = idx >> 2, h = idx & 3;
    int d = (e < E) ? __ldg(dst + e) : e - E;
    float m = fdec(d_menc[(size_t)d * 4 + h]);
    float p = __expf(d_p[idx] - m);
    d_p[idx] = p;
    atomicAdd(&d_denom[(size_t)d * 4 + h], p);
}

// pass 3: acc[d] += (p/denom[d]) * xl[s]  (warp per edge)
__global__ void k_agg(const int* __restrict__ src, const int* __restrict__ dst,
                      int E, int N) {
    int warp = (blockIdx.x * blockDim.x + threadIdx.x) >> 5;
    int lane = threadIdx.x & 31;
    int tot = E + N;
    if (warp >= tot) return;
    int s, d;
    if (warp < E) { s = __ldg(src + warp); d = __ldg(dst + warp); }
    else { s = d = warp - E; }

    float4 pe = *(const float4*)(d_p + (size_t)warp * 4);
    float4 dn = *(const float4*)(d_denom + (size_t)d * 4);
    bool lo = lane < 16;
    float aA = lo ? __fdividef(pe.x, dn.x) : __fdividef(pe.y, dn.y);  // head lane>>4
    float aB = lo ? __fdividef(pe.z, dn.z) : __fdividef(pe.w, dn.w);  // head 2+(lane>>4)

    const float4* xls = (const float4*)(d_xl + (size_t)s * 256);
    float4 x1 = xls[lane], x2 = xls[lane + 32];
    float* ap = d_acc + (size_t)d * 256 + lane * 4;
    atomicAdd(ap + 0, x1.x * aA);
    atomicAdd(ap + 1, x1.y * aA);
    atomicAdd(ap + 2, x1.z * aA);
    atomicAdd(ap + 3, x1.w * aA);
    float* ap2 = ap + 128;
    atomicAdd(ap2 + 0, x2.x * aB);
    atomicAdd(ap2 + 1, x2.y * aB);
    atomicAdd(ap2 + 2, x2.z * aB);
    atomicAdd(ap2 + 3, x2.w * aB);
}

// head mean + b_gat + relu + linear head (warp per node)
__global__ void k_final(const float* __restrict__ b_gat,
                        const float* __restrict__ W_lin,
                        const float* __restrict__ b_lin,
                        float* __restrict__ out, int N) {
    int warp = (blockIdx.x * blockDim.x + threadIdx.x) >> 5;
    int lane = threadIdx.x & 31;
    if (warp >= N) return;
    const float* a = d_acc + (size_t)warp * 256;
    float r = 0.f;
    #pragma unroll
    for (int j = 0; j < 2; j++) {
        int c = lane + j * 32;
        float s = a[c] + a[64 + c] + a[128 + c] + a[192 + c];
        float v = fmaxf(s * 0.25f + b_gat[c], 0.f);
        r += v * W_lin[c];
    }
    #pragma unroll
    for (int m = 16; m; m >>= 1) r += __shfl_xor_sync(0xffffffffu, r, m);
    if (lane == 0) out[warp] = r + b_lin[0];
}

// ---------------------------------------------------------------------------
extern "C" void kernel_launch(void* const* d_in, const int* in_sizes, int n_in,
                              void* d_out, int out_size) {
    const float* x     = (const float*)d_in[0];
    const int*   ei    = (const int*)d_in[1];
    // d_in[2] edge_attr: unused by reference
    const float* W_gcn = (const float*)d_in[3];
    const float* b_gcn = (const float*)d_in[4];
    const float* W_l   = (const float*)d_in[5];
    const float* b_l   = (const float*)d_in[6];
    const float* W_r   = (const float*)d_in[7];
    const float* b_r   = (const float*)d_in[8];
    const float* att   = (const float*)d_in[9];
    const float* b_gat = (const float*)d_in[10];
    const float* W_lin = (const float*)d_in[11];
    const float* b_lin = (const float*)d_in[12];

    int N = in_sizes[0] / 128;
    int E = in_sizes[1] / 2;
    const int* src = ei;
    const int* dst = ei + E;
    float* out = (float*)d_out;
    int tot = E + N;

    k_zero<<<(N * 64 + 255) / 256, 256>>>(N);

    dim3 gg((N + 31) / 32, 1);
    k_gemm_gcn<<<gg, 128>>>(x, W_gcn, N);

    k_deg<<<(E + 255) / 256, 256>>>(dst, E);
    k_dinv<<<(N + 255) / 256, 256>>>(N);
    k_gcn_init<<<(N * 64 + 255) / 256, 256>>>(N);
    k_gcn_edge<<<(E * 16 + 255) / 256, 256>>>(src, dst, E);

    dim3 gl((N + 31) / 32, 4);
    k_gemm_gat<<<gl, 128>>>(W_l, b_gcn, b_l, 0, N);
    k_gemm_gat<<<gl, 128>>>(W_r, b_gcn, b_r, 1, N);

    k_logits<<<(tot * 32 + 255) / 256, 256>>>(src, dst, att, E, N);
    k_softmax<<<(tot * 4 + 255) / 256, 256>>>(dst, E, N);
    k_agg<<<(tot * 32 + 255) / 256, 256>>>(src, dst, E, N);
    k_final<<<(N * 32 + 255) / 256, 256>>>(b_gat, W_lin, b_lin, out, N);
}

// round 5
// speedup vs baseline: 2.2898x; 2.2898x over previous
#include <cuda_runtime.h>
#include <cstddef>
#include <math_constants.h>

// ---------------------------------------------------------------------------
// CarbonGNN: GCNConv -> ReLU -> GATv2Conv(heads=4, concat=False) -> ReLU -> Linear
// N=50000, E=800000, IN=128, HID=64, H=4, neg_slope=0.2
// CSR-by-dst design: counting sort -> warp-per-node register aggregation,
// online softmax (no atomics in any aggregation, single gather per edge).
// ---------------------------------------------------------------------------

#define MAXN 50000
#define MAXE 800000

// Scratch (device globals: allocation-free)
__device__ float d_xw[MAXN * 64];            // x @ W_gcn
__device__ float d_g1[MAXN * 64];            // GCN output (pre-bias/relu)
__device__ float d_dinv[MAXN];
__device__ int   d_deg[MAXN];
__device__ int   d_off[MAXN + 1];            // CSR row offsets (deg+1 incl. self loop)
__device__ int   d_cur[MAXN];                // scatter cursors
__device__ int   d_csr_src[MAXE + MAXN];     // src node per CSR slot
__device__ float d_xl[MAXN * 256];           // lin_l(h)  [N, H*HID]
__device__ float d_xr[MAXN * 256];           // lin_r(h)

// ---------------------------------------------------------------------------
__global__ void k_zero_deg(int N) {
    int i = blockIdx.x * blockDim.x + threadIdx.x;
    if (i < N) d_deg[i] = 0;
}

__global__ void k_deg(const int* __restrict__ dst, int E) {
    int e = blockIdx.x * blockDim.x + threadIdx.x;
    if (e < E) atomicAdd(&d_deg[__ldg(dst + e)], 1);
}

// Single-block scan: offsets (deg+1 per node, incl. self loop), cursors, dinv.
__global__ void k_scan(int N) {
    __shared__ int ssum[1024];
    int t = threadIdx.x;
    int chunk = (N + 1023) >> 10;
    int s = t * chunk, e = min(N, s + chunk);
    int loc = 0;
    for (int i = s; i < e; i++) loc += d_deg[i] + 1;
    ssum[t] = loc;
    __syncthreads();
    for (int o = 1; o < 1024; o <<= 1) {
        int u = (t >= o) ? ssum[t - o] : 0;
        __syncthreads();
        ssum[t] += u;
        __syncthreads();
    }
    int run = ssum[t] - loc;   // exclusive prefix
    for (int i = s; i < e; i++) {
        d_off[i] = run;
        d_cur[i] = run;
        d_dinv[i] = rsqrtf((float)d_deg[i] + 1.0f);
        run += d_deg[i] + 1;
    }
    if (t == 1023) d_off[N] = ssum[1023];
}

// Scatter edges (and self-loops) into CSR-by-dst.
__global__ void k_scatter(const int* __restrict__ src,
                          const int* __restrict__ dst, int E, int N) {
    int idx = blockIdx.x * blockDim.x + threadIdx.x;
    if (idx >= E + N) return;
    int s, d;
    if (idx < E) { s = __ldg(src + idx); d = __ldg(dst + idx); }
    else { s = idx - E; d = s; }
    int pos = atomicAdd(&d_cur[d], 1);
    d_csr_src[pos] = s;
}

// ---------------------------------------------------------------------------
// Tiled fp32 GEMM: C[M,NC] = act(A[M,BK]) @ W[BK,NC] (+bout)
template <int BK, bool RELU_IN>
__device__ __forceinline__ void gemm_body(
    const float* __restrict__ A, const float* __restrict__ W,
    const float* __restrict__ bin, const float* __restrict__ bout,
    float* __restrict__ C, int M, int NC)
{
    __shared__ float As[32 * 32];
    __shared__ float Ws[32 * 64];
    const int t = threadIdx.x;
    const int row0 = blockIdx.x * 32;
    const int c0 = blockIdx.y * 64;
    const int tc = t & 15;
    const int tr = t >> 4;
    float acc[4][4] = {};

    for (int kc = 0; kc < BK; kc += 32) {
        {
            int r = t >> 2, q4 = t & 3;
            int grow = row0 + r;
            #pragma unroll
            for (int half = 0; half < 2; half++) {
                int q = q4 + half * 4;
                float4 v = make_float4(0.f, 0.f, 0.f, 0.f);
                if (grow < M)
                    v = *(const float4*)(A + (size_t)grow * BK + kc + q * 4);
                if (RELU_IN) {
                    const float* bb = bin + kc + q * 4;
                    v.x = fmaxf(v.x + bb[0], 0.f);
                    v.y = fmaxf(v.y + bb[1], 0.f);
                    v.z = fmaxf(v.z + bb[2], 0.f);
                    v.w = fmaxf(v.w + bb[3], 0.f);
                }
                *(float4*)(As + r * 32 + q * 4) = v;
            }
        }
        {
            int k = t >> 4, q2 = t & 15;
            #pragma unroll
            for (int i = 0; i < 4; i++) {
                int kk = k + i * 8;
                *(float4*)(Ws + kk * 64 + q2 * 4) =
                    *(const float4*)(W + (size_t)(kc + kk) * NC + c0 + q2 * 4);
            }
        }
        __syncthreads();
        #pragma unroll
        for (int kk = 0; kk < 32; kk += 4) {
            float4 a[4], w[4];
            #pragma unroll
            for (int r = 0; r < 4; r++)
                a[r] = *(const float4*)(As + (tr * 4 + r) * 32 + kk);
            #pragma unroll
            for (int j = 0; j < 4; j++)
                w[j] = *(const float4*)(Ws + (kk + j) * 64 + tc * 4);
            #pragma unroll
            for (int r = 0; r < 4; r++) {
                acc[r][0] += a[r].x * w[0].x + a[r].y * w[1].x + a[r].z * w[2].x + a[r].w * w[3].x;
                acc[r][1] += a[r].x * w[0].y + a[r].y * w[1].y + a[r].z * w[2].y + a[r].w * w[3].y;
                acc[r][2] += a[r].x * w[0].z + a[r].y * w[1].z + a[r].z * w[2].z + a[r].w * w[3].z;
                acc[r][3] += a[r].x * w[0].w + a[r].y * w[1].w + a[r].z * w[2].w + a[r].w * w[3].w;
            }
        }
        __syncthreads();
    }

    #pragma unroll
    for (int r = 0; r < 4; r++) {
        int grow = row0 + tr * 4 + r;
        if (grow < M) {
            float4 o = make_float4(acc[r][0], acc[r][1], acc[r][2], acc[r][3]);
            if (bout) {
                const float* bb = bout + c0 + tc * 4;
                o.x += bb[0]; o.y += bb[1]; o.z += bb[2]; o.w += bb[3];
            }
            *(float4*)(C + (size_t)grow * NC + c0 + tc * 4) = o;
        }
    }
}

__global__ void k_gemm_gcn(const float* __restrict__ x,
                           const float* __restrict__ Wg, int M) {
    gemm_body<128, false>(x, Wg, nullptr, nullptr, d_xw, M, 64);
}

__global__ void k_gemm_gat(const float* __restrict__ Wlr,
                           const float* __restrict__ bgcn,
                           const float* __restrict__ blr, int which, int M) {
    gemm_body<64, true>(d_g1, Wlr, bgcn, blr, which ? d_xr : d_xl, M, 256);
}

// ---------------------------------------------------------------------------
// GCN aggregation, warp per node (self-loop is a CSR slot with s==d):
// g1[d,c] = dinv[d] * sum_slots dinv[s] * xw[s,c]
__global__ void k_gcn_csr(int N) {
    int warp = (blockIdx.x * blockDim.x + threadIdx.x) >> 5;
    int lane = threadIdx.x & 31;
    if (warp >= N) return;
    int beg = d_off[warp], end = d_off[warp + 1];
    float2 acc = make_float2(0.f, 0.f);
    for (int base = beg; base < end; base += 32) {
        int sv = (base + lane < end) ? d_csr_src[base + lane] : 0;
        int cnt = min(32, end - base);
        for (int j = 0; j < cnt; j++) {
            int s = __shfl_sync(0xffffffffu, sv, j);
            float2 v = *(const float2*)(d_xw + (size_t)s * 64 + lane * 2);
            float w = d_dinv[s];
            acc.x += v.x * w;
            acc.y += v.y * w;
        }
    }
    float wd = d_dinv[warp];
    *(float2*)(d_g1 + (size_t)warp * 64 + lane * 2) =
        make_float2(acc.x * wd, acc.y * wd);
}

// ---------------------------------------------------------------------------
// Fused GATv2: warp per node, online softmax, single pass over incoming edges.
// Value layout v = h*64+c. Lane owns float4 at v=4*lane (head = lane>>4) and
// v=128+4*lane (head = 2+(lane>>4)). The 16-lane xor reduction leaves the
// per-head logit replicated across each half-warp, matching the accumulators.
__global__ void k_gat_csr(const float* __restrict__ att,
                          const float* __restrict__ b_gat,
                          const float* __restrict__ W_lin,
                          const float* __restrict__ b_lin,
                          float* __restrict__ out, int N) {
    __shared__ float satt[256];
    if (threadIdx.x < 256) satt[threadIdx.x] = att[threadIdx.x];
    __syncthreads();
    int warp = (blockIdx.x * blockDim.x + threadIdx.x) >> 5;
    int lane = threadIdx.x & 31;
    if (warp >= N) return;

    const float4* at4 = (const float4*)satt;
    float4 t1 = at4[lane], t2 = at4[lane + 32];
    const float4* xr4 = (const float4*)(d_xr + (size_t)warp * 256);
    float4 b1 = xr4[lane], b2 = xr4[lane + 32];

    float m1 = -CUDART_INF_F, m2 = -CUDART_INF_F;
    float den1 = 0.f, den2 = 0.f;
    float4 acc1 = make_float4(0.f, 0.f, 0.f, 0.f);
    float4 acc2 = make_float4(0.f, 0.f, 0.f, 0.f);

    int beg = d_off[warp], end = d_off[warp + 1];
    for (int base = beg; base < end; base += 32) {
        int sv = (base + lane < end) ? d_csr_src[base + lane] : 0;
        int cnt = min(32, end - base);
        for (int j = 0; j < cnt; j++) {
            int s = __shfl_sync(0xffffffffu, sv, j);
            const float4* xl4 = (const float4*)(d_xl + (size_t)s * 256);
            float4 a1 = xl4[lane], a2 = xl4[lane + 32];

            auto lr = [](float v) { return v > 0.f ? v : 0.2f * v; };
            float p1 = lr(a1.x + b1.x) * t1.x + lr(a1.y + b1.y) * t1.y
                     + lr(a1.z + b1.z) * t1.z + lr(a1.w + b1.w) * t1.w;
            float p2 = lr(a2.x + b2.x) * t2.x + lr(a2.y + b2.y) * t2.y
                     + lr(a2.z + b2.z) * t2.z + lr(a2.w + b2.w) * t2.w;
            #pragma unroll
            for (int msk = 8; msk; msk >>= 1) {
                p1 += __shfl_xor_sync(0xffffffffu, p1, msk);
                p2 += __shfl_xor_sync(0xffffffffu, p2, msk);
            }
            // online softmax update, head group 1
            {
                float nm = fmaxf(m1, p1);
                float sc = __expf(m1 - nm);
                float w  = __expf(p1 - nm);
                den1 = den1 * sc + w;
                acc1.x = acc1.x * sc + w * a1.x;
                acc1.y = acc1.y * sc + w * a1.y;
                acc1.z = acc1.z * sc + w * a1.z;
                acc1.w = acc1.w * sc + w * a1.w;
                m1 = nm;
            }
            // head group 2
            {
                float nm = fmaxf(m2, p2);
                float sc = __expf(m2 - nm);
                float w  = __expf(p2 - nm);
                den2 = den2 * sc + w;
                acc2.x = acc2.x * sc + w * a2.x;
                acc2.y = acc2.y * sc + w * a2.y;
                acc2.z = acc2.z * sc + w * a2.z;
                acc2.w = acc2.w * sc + w * a2.w;
                m2 = nm;
            }
        }
    }

    float i1 = __fdividef(1.f, den1);
    float i2 = __fdividef(1.f, den2);
    // lane l (<16) holds heads {0,2} at c=4l; lane l+16 holds heads {1,3} at same c
    float4 t;
    t.x = acc1.x * i1 + acc2.x * i2;
    t.y = acc1.y * i1 + acc2.y * i2;
    t.z = acc1.z * i1 + acc2.z * i2;
    t.w = acc1.w * i1 + acc2.w * i2;
    t.x += __shfl_xor_sync(0xffffffffu, t.x, 16);
    t.y += __shfl_xor_sync(0xffffffffu, t.y, 16);
    t.z += __shfl_xor_sync(0xffffffffu, t.z, 16);
    t.w += __shfl_xor_sync(0xffffffffu, t.w, 16);

    int c = (lane & 15) * 4;
    float4 bg = *(const float4*)(b_gat + c);
    float4 wl = *(const float4*)(W_lin + c);
    float partial =
        fmaxf(t.x * 0.25f + bg.x, 0.f) * wl.x +
        fmaxf(t.y * 0.25f + bg.y, 0.f) * wl.y +
        fmaxf(t.z * 0.25f + bg.z, 0.f) * wl.z +
        fmaxf(t.w * 0.25f + bg.w, 0.f) * wl.w;
    #pragma unroll
    for (int msk = 8; msk; msk >>= 1)
        partial += __shfl_xor_sync(0xffffffffu, partial, msk);
    if (lane == 0) out[warp] = partial + b_lin[0];
}

// ---------------------------------------------------------------------------
extern "C" void kernel_launch(void* const* d_in, const int* in_sizes, int n_in,
                              void* d_out, int out_size) {
    const float* x     = (const float*)d_in[0];
    const int*   ei    = (const int*)d_in[1];
    // d_in[2] edge_attr: unused by reference
    const float* W_gcn = (const float*)d_in[3];
    const float* b_gcn = (const float*)d_in[4];
    const float* W_l   = (const float*)d_in[5];
    const float* b_l   = (const float*)d_in[6];
    const float* W_r   = (const float*)d_in[7];
    const float* b_r   = (const float*)d_in[8];
    const float* att   = (const float*)d_in[9];
    const float* b_gat = (const float*)d_in[10];
    const float* W_lin = (const float*)d_in[11];
    const float* b_lin = (const float*)d_in[12];

    int N = in_sizes[0] / 128;
    int E = in_sizes[1] / 2;
    const int* src = ei;
    const int* dst = ei + E;
    float* out = (float*)d_out;

    // CSR build
    k_zero_deg<<<(N + 255) / 256, 256>>>(N);
    k_deg<<<(E + 255) / 256, 256>>>(dst, E);
    k_scan<<<1, 1024>>>(N);
    k_scatter<<<(E + N + 255) / 256, 256>>>(src, dst, E, N);

    // GCN
    dim3 gg((N + 31) / 32, 1);
    k_gemm_gcn<<<gg, 128>>>(x, W_gcn, N);
    k_gcn_csr<<<(N * 32 + 255) / 256, 256>>>(N);

    // GAT projections
    dim3 gl((N + 31) / 32, 4);
    k_gemm_gat<<<gl, 128>>>(W_l, b_gcn, b_l, 0, N);
    k_gemm_gat<<<gl, 128>>>(W_r, b_gcn, b_r, 1, N);

    // Fused GATv2 + head mean + output head
    k_gat_csr<<<(N * 32 + 255) / 256, 256>>>(att, b_gat, W_lin, b_lin, out, N);
}

// round 16
// speedup vs baseline: 2.2939x; 1.0018x over previous
#include <cuda_runtime.h>
#include <cstddef>
#include <math_constants.h>

// ---------------------------------------------------------------------------
// CarbonGNN: GCNConv -> ReLU -> GATv2Conv(heads=4, concat=False) -> ReLU -> Linear
// N=50000, E=800000, IN=128, HID=64, H=4, neg_slope=0.2
// R12: byte-identical device code to the verified 406us R5 kernel.
// Host side adds a size-signature check with stable-order fallback input
// resolution (no-op when the canonical metadata order holds).
// ---------------------------------------------------------------------------

#define MAXN 50000
#define MAXE 800000

// Scratch (device globals: allocation-free)
__device__ float d_xw[MAXN * 64];            // x @ W_gcn
__device__ float d_g1[MAXN * 64];            // GCN output (pre-bias/relu)
__device__ float d_dinv[MAXN];
__device__ int   d_deg[MAXN];
__device__ int   d_off[MAXN + 1];            // CSR row offsets (deg+1 incl. self loop)
__device__ int   d_cur[MAXN];                // scatter cursors
__device__ int   d_csr_src[MAXE + MAXN];     // src node per CSR slot
__device__ float d_xl[MAXN * 256];           // lin_l(h)  [N, H*HID]
__device__ float d_xr[MAXN * 256];           // lin_r(h)

// ---------------------------------------------------------------------------
__global__ void k_zero_deg(int N) {
    int i = blockIdx.x * blockDim.x + threadIdx.x;
    if (i < N) d_deg[i] = 0;
}

__global__ void k_deg(const int* __restrict__ dst, int E) {
    int e = blockIdx.x * blockDim.x + threadIdx.x;
    if (e < E) atomicAdd(&d_deg[__ldg(dst + e)], 1);
}

// Single-block scan: offsets (deg+1 per node, incl. self loop), cursors, dinv.
__global__ void k_scan(int N) {
    __shared__ int ssum[1024];
    int t = threadIdx.x;
    int chunk = (N + 1023) >> 10;
    int s = t * chunk, e = min(N, s + chunk);
    int loc = 0;
    for (int i = s; i < e; i++) loc += d_deg[i] + 1;
    ssum[t] = loc;
    __syncthreads();
    for (int o = 1; o < 1024; o <<= 1) {
        int u = (t >= o) ? ssum[t - o] : 0;
        __syncthreads();
        ssum[t] += u;
        __syncthreads();
    }
    int run = ssum[t] - loc;   // exclusive prefix
    for (int i = s; i < e; i++) {
        d_off[i] = run;
        d_cur[i] = run;
        d_dinv[i] = rsqrtf((float)d_deg[i] + 1.0f);
        run += d_deg[i] + 1;
    }
    if (t == 1023) d_off[N] = ssum[1023];
}

// Scatter edges (and self-loops) into CSR-by-dst.
__global__ void k_scatter(const int* __restrict__ src,
                          const int* __restrict__ dst, int E, int N) {
    int idx = blockIdx.x * blockDim.x + threadIdx.x;
    if (idx >= E + N) return;
    int s, d;
    if (idx < E) { s = __ldg(src + idx); d = __ldg(dst + idx); }
    else { s = idx - E; d = s; }
    int pos = atomicAdd(&d_cur[d], 1);
    d_csr_src[pos] = s;
}

// ---------------------------------------------------------------------------
// Tiled fp32 GEMM: C[M,NC] = act(A[M,BK]) @ W[BK,NC] (+bout)
template <int BK, bool RELU_IN>
__device__ __forceinline__ void gemm_body(
    const float* __restrict__ A, const float* __restrict__ W,
    const float* __restrict__ bin, const float* __restrict__ bout,
    float* __restrict__ C, int M, int NC)
{
    __shared__ float As[32 * 32];
    __shared__ float Ws[32 * 64];
    const int t = threadIdx.x;
    const int row0 = blockIdx.x * 32;
    const int c0 = blockIdx.y * 64;
    const int tc = t & 15;
    const int tr = t >> 4;
    float acc[4][4] = {};

    for (int kc = 0; kc < BK; kc += 32) {
        {
            int r = t >> 2, q4 = t & 3;
            int grow = row0 + r;
            #pragma unroll
            for (int half = 0; half < 2; half++) {
                int q = q4 + half * 4;
                float4 v = make_float4(0.f, 0.f, 0.f, 0.f);
                if (grow < M)
                    v = *(const float4*)(A + (size_t)grow * BK + kc + q * 4);
                if (RELU_IN) {
                    const float* bb = bin + kc + q * 4;
                    v.x = fmaxf(v.x + bb[0], 0.f);
                    v.y = fmaxf(v.y + bb[1], 0.f);
                    v.z = fmaxf(v.z + bb[2], 0.f);
                    v.w = fmaxf(v.w + bb[3], 0.f);
                }
                *(float4*)(As + r * 32 + q * 4) = v;
            }
        }
        {
            int k = t >> 4, q2 = t & 15;
            #pragma unroll
            for (int i = 0; i < 4; i++) {
                int kk = k + i * 8;
                *(float4*)(Ws + kk * 64 + q2 * 4) =
                    *(const float4*)(W + (size_t)(kc + kk) * NC + c0 + q2 * 4);
            }
        }
        __syncthreads();
        #pragma unroll
        for (int kk = 0; kk < 32; kk += 4) {
            float4 a[4], w[4];
            #pragma unroll
            for (int r = 0; r < 4; r++)
                a[r] = *(const float4*)(As + (tr * 4 + r) * 32 + kk);
            #pragma unroll
            for (int j = 0; j < 4; j++)
                w[j] = *(const float4*)(Ws + (kk + j) * 64 + tc * 4);
            #pragma unroll
            for (int r = 0; r < 4; r++) {
                acc[r][0] += a[r].x * w[0].x + a[r].y * w[1].x + a[r].z * w[2].x + a[r].w * w[3].x;
                acc[r][1] += a[r].x * w[0].y + a[r].y * w[1].y + a[r].z * w[2].y + a[r].w * w[3].y;
                acc[r][2] += a[r].x * w[0].z + a[r].y * w[1].z + a[r].z * w[2].z + a[r].w * w[3].z;
                acc[r][3] += a[r].x * w[0].w + a[r].y * w[1].w + a[r].z * w[2].w + a[r].w * w[3].w;
            }
        }
        __syncthreads();
    }

    #pragma unroll
    for (int r = 0; r < 4; r++) {
        int grow = row0 + tr * 4 + r;
        if (grow < M) {
            float4 o = make_float4(acc[r][0], acc[r][1], acc[r][2], acc[r][3]);
            if (bout) {
                const float* bb = bout + c0 + tc * 4;
                o.x += bb[0]; o.y += bb[1]; o.z += bb[2]; o.w += bb[3];
            }
            *(float4*)(C + (size_t)grow * NC + c0 + tc * 4) = o;
        }
    }
}

__global__ void k_gemm_gcn(const float* __restrict__ x,
                           const float* __restrict__ Wg, int M) {
    gemm_body<128, false>(x, Wg, nullptr, nullptr, d_xw, M, 64);
}

__global__ void k_gemm_gat(const float* __restrict__ Wlr,
                           const float* __restrict__ bgcn,
                           const float* __restrict__ blr, int which, int M) {
    gemm_body<64, true>(d_g1, Wlr, bgcn, blr, which ? d_xr : d_xl, M, 256);
}

// ---------------------------------------------------------------------------
// GCN aggregation, warp per node (self-loop is a CSR slot with s==d):
// g1[d,c] = dinv[d] * sum_slots dinv[s] * xw[s,c]
__global__ void k_gcn_csr(int N) {
    int warp = (blockIdx.x * blockDim.x + threadIdx.x) >> 5;
    int lane = threadIdx.x & 31;
    if (warp >= N) return;
    int beg = d_off[warp], end = d_off[warp + 1];
    float2 acc = make_float2(0.f, 0.f);
    for (int base = beg; base < end; base += 32) {
        int sv = (base + lane < end) ? d_csr_src[base + lane] : 0;
        int cnt = min(32, end - base);
        for (int j = 0; j < cnt; j++) {
            int s = __shfl_sync(0xffffffffu, sv, j);
            float2 v = *(const float2*)(d_xw + (size_t)s * 64 + lane * 2);
            float w = d_dinv[s];
            acc.x += v.x * w;
            acc.y += v.y * w;
        }
    }
    float wd = d_dinv[warp];
    *(float2*)(d_g1 + (size_t)warp * 64 + lane * 2) =
        make_float2(acc.x * wd, acc.y * wd);
}

// ---------------------------------------------------------------------------
// Fused GATv2: warp per node, online softmax, single pass over incoming edges.
__global__ void k_gat_csr(const float* __restrict__ att,
                          const float* __restrict__ b_gat,
                          const float* __restrict__ W_lin,
                          const float* __restrict__ b_lin,
                          float* __restrict__ out, int N) {
    __shared__ float satt[256];
    if (threadIdx.x < 256) satt[threadIdx.x] = att[threadIdx.x];
    __syncthreads();
    int warp = (blockIdx.x * blockDim.x + threadIdx.x) >> 5;
    int lane = threadIdx.x & 31;
    if (warp >= N) return;

    const float4* at4 = (const float4*)satt;
    float4 t1 = at4[lane], t2 = at4[lane + 32];
    const float4* xr4 = (const float4*)(d_xr + (size_t)warp * 256);
    float4 b1 = xr4[lane], b2 = xr4[lane + 32];

    float m1 = -CUDART_INF_F, m2 = -CUDART_INF_F;
    float den1 = 0.f, den2 = 0.f;
    float4 acc1 = make_float4(0.f, 0.f, 0.f, 0.f);
    float4 acc2 = make_float4(0.f, 0.f, 0.f, 0.f);

    int beg = d_off[warp], end = d_off[warp + 1];
    for (int base = beg; base < end; base += 32) {
        int sv = (base + lane < end) ? d_csr_src[base + lane] : 0;
        int cnt = min(32, end - base);
        for (int j = 0; j < cnt; j++) {
            int s = __shfl_sync(0xffffffffu, sv, j);
            const float4* xl4 = (const float4*)(d_xl + (size_t)s * 256);
            float4 a1 = xl4[lane], a2 = xl4[lane + 32];

            auto lr = [](float v) { return v > 0.f ? v : 0.2f * v; };
            float p1 = lr(a1.x + b1.x) * t1.x + lr(a1.y + b1.y) * t1.y
                     + lr(a1.z + b1.z) * t1.z + lr(a1.w + b1.w) * t1.w;
            float p2 = lr(a2.x + b2.x) * t2.x + lr(a2.y + b2.y) * t2.y
                     + lr(a2.z + b2.z) * t2.z + lr(a2.w + b2.w) * t2.w;
            #pragma unroll
            for (int msk = 8; msk; msk >>= 1) {
                p1 += __shfl_xor_sync(0xffffffffu, p1, msk);
                p2 += __shfl_xor_sync(0xffffffffu, p2, msk);
            }
            {
                float nm = fmaxf(m1, p1);
                float sc = __expf(m1 - nm);
                float w  = __expf(p1 - nm);
                den1 = den1 * sc + w;
                acc1.x = acc1.x * sc + w * a1.x;
                acc1.y = acc1.y * sc + w * a1.y;
                acc1.z = acc1.z * sc + w * a1.z;
                acc1.w = acc1.w * sc + w * a1.w;
                m1 = nm;
            }
            {
                float nm = fmaxf(m2, p2);
                float sc = __expf(m2 - nm);
                float w  = __expf(p2 - nm);
                den2 = den2 * sc + w;
                acc2.x = acc2.x * sc + w * a2.x;
                acc2.y = acc2.y * sc + w * a2.y;
                acc2.z = acc2.z * sc + w * a2.z;
                acc2.w = acc2.w * sc + w * a2.w;
                m2 = nm;
            }
        }
    }

    float i1 = __fdividef(1.f, den1);
    float i2 = __fdividef(1.f, den2);
    float4 t;
    t.x = acc1.x * i1 + acc2.x * i2;
    t.y = acc1.y * i1 + acc2.y * i2;
    t.z = acc1.z * i1 + acc2.z * i2;
    t.w = acc1.w * i1 + acc2.w * i2;
    t.x += __shfl_xor_sync(0xffffffffu, t.x, 16);
    t.y += __shfl_xor_sync(0xffffffffu, t.y, 16);
    t.z += __shfl_xor_sync(0xffffffffu, t.z, 16);
    t.w += __shfl_xor_sync(0xffffffffu, t.w, 16);

    int c = (lane & 15) * 4;
    float4 bg = *(const float4*)(b_gat + c);
    float4 wl = *(const float4*)(W_lin + c);
    float partial =
        fmaxf(t.x * 0.25f + bg.x, 0.f) * wl.x +
        fmaxf(t.y * 0.25f + bg.y, 0.f) * wl.y +
        fmaxf(t.z * 0.25f + bg.z, 0.f) * wl.z +
        fmaxf(t.w * 0.25f + bg.w, 0.f) * wl.w;
    #pragma unroll
    for (int msk = 8; msk; msk >>= 1)
        partial += __shfl_xor_sync(0xffffffffu, partial, msk);
    if (lane == 0) out[warp] = partial + b_lin[0];
}

// ---------------------------------------------------------------------------
extern "C" void kernel_launch(void* const* d_in, const int* in_sizes, int n_in,
                              void* d_out, int out_size) {
    // Canonical metadata order:
    // 0 x[N*128] 1 edge_index[2E] 2 edge_attr[E] 3 W_gcn[8192] 4 b_gcn[64]
    // 5 W_l[16384] 6 b_l[256] 7 W_r[16384] 8 b_r[256] 9 att[256]
    // 10 b_gat[64] 11 W_lin[64] 12 b_lin[1]
    int ix = 0, iei = 1, iWg = 3, ibg = 4, iWl = 5, ibl = 6, iWr = 7,
        ibr = 8, iatt = 9, ibgat = 10, iWlin = 11, iblin = 12;

    bool canon = (n_in >= 13 &&
                  in_sizes[3] == 8192  && in_sizes[4] == 64  &&
                  in_sizes[5] == 16384 && in_sizes[6] == 256 &&
                  in_sizes[7] == 16384 && in_sizes[8] == 256 &&
                  in_sizes[9] == 256   && in_sizes[10] == 64 &&
                  in_sizes[11] == 64   && in_sizes[12] == 1);
    if (!canon) {
        // Fallback: resolve by size, stable order. x = largest, edge_index =
        // second largest; ties among equal small sizes keep original order.
        int xi = 0; long best = -1;
        for (int i = 0; i < n_in; i++)
            if ((long)in_sizes[i] > best) { best = in_sizes[i]; xi = i; }
        int e2 = -1; long best2 = -1;
        for (int i = 0; i < n_in; i++)
            if (i != xi && (long)in_sizes[i] > best2) { best2 = in_sizes[i]; e2 = i; }
        ix = xi; iei = e2;
        int c16k = 0, c256 = 0, c64 = 0;
        for (int i = 0; i < n_in; i++) {
            if (i == ix || i == iei) continue;
            int s = in_sizes[i];
            if (s == 8192) iWg = i;
            else if (s == 16384) { if (c16k == 0) iWl = i; else iWr = i; c16k++; }
            else if (s == 256) {
                if (c256 == 0) ibl = i; else if (c256 == 1) ibr = i; else iatt = i;
                c256++;
            } else if (s == 64) {
                if (c64 == 0) ibg = i; else if (c64 == 1) ibgat = i; else iWlin = i;
                c64++;
            } else if (s == 1) iblin = i;
        }
    }

    const float* x     = (const float*)d_in[ix];
    const int*   ei    = (const int*)d_in[iei];
    const float* W_gcn = (const float*)d_in[iWg];
    const float* b_gcn = (const float*)d_in[ibg];
    const float* W_l   = (const float*)d_in[iWl];
    const float* b_l   = (const float*)d_in[ibl];
    const float* W_r   = (const float*)d_in[iWr];
    const float* b_r   = (const float*)d_in[ibr];
    const float* att   = (const float*)d_in[iatt];
    const float* b_gat = (const float*)d_in[ibgat];
    const float* W_lin = (const float*)d_in[iWlin];
    const float* b_lin = (const float*)d_in[iblin];

    int N = in_sizes[ix] / 128;
    int E = in_sizes[iei] / 2;
    if (N > MAXN) N = MAXN;
    if (E > MAXE) E = MAXE;
    const int* src = ei;
    const int* dst = ei + E;
    float* out = (float*)d_out;

    // CSR build
    k_zero_deg<<<(N + 255) / 256, 256>>>(N);
    k_deg<<<(E + 255) / 256, 256>>>(dst, E);
    k_scan<<<1, 1024>>>(N);
    k_scatter<<<(E + N + 255) / 256, 256>>>(src, dst, E, N);

    // GCN
    dim3 gg((N + 31) / 32, 1);
    k_gemm_gcn<<<gg, 128>>>(x, W_gcn, N);
    k_gcn_csr<<<(N * 32 + 255) / 256, 256>>>(N);

    // GAT projections
    dim3 gl((N + 31) / 32, 4);
    k_gemm_gat<<<gl, 128>>>(W_l, b_gcn, b_l, 0, N);
    k_gemm_gat<<<gl, 128>>>(W_r, b_gcn, b_r, 1, N);

    // Fused GATv2 + head mean + output head
    k_gat_csr<<<(N * 32 + 255) / 256, 256>>>(att, b_gat, W_lin, b_lin, out, N);
}